// round 1
// baseline (speedup 1.0000x reference)
#include <cuda_runtime.h>
#include <math.h>
#include <stdint.h>

// ---------------------------------------------------------------------------
// QuantSoftmax: B=32, C=128, H=W=80 (HW=6400). int32 input (int8 repr, zp=0),
// float32 output. Piecewise-quantized exp (qint16) + reciprocal (qint16),
// requantized to int8*OUT_SCALE.
//
// Since data is integer and zp=0: xd = -(qmax - q)*ds takes only 256 values.
// Prologue kernel builds exp LUT (depends on ds) + recip tables once.
// ---------------------------------------------------------------------------

#define C_DIM 128
#define HW_DIM 6400
#define NTHREADS 128   // pixels per block
#define KROWS 64       // 128 channels / 2 per u32

__device__ float g_exp_lut[256];   // quantized exp value (integer-valued float)
__device__ float g_rtab1[256];     // recip table, region (0.1, 250)
__device__ float g_rtab2[256];     // recip table, region (250, 500)

__device__ __forceinline__ float quant_i16(float y, float scale) {
    float q = rintf(__fdiv_rn(y, scale));           // jnp.round = half-even
    return fminf(fmaxf(q, -32768.0f), 32767.0f);
}

__device__ __forceinline__ float exp_f32(float x) {
    return (float)exp((double)x);                   // ~correctly-rounded f32 exp
}

// one block, 256 threads: build LUTs
__global__ void build_luts_kernel(const float* __restrict__ ds_ptr) {
    int i = threadIdx.x;                            // 0..255
    float ds = ds_ptr[0];
    const float ESCALE = (float)(2.0 / 65535.0);
    const float RSCALE = (float)((1.0 / 0.1) * 2.0 / 65535.0);

    // ---- exp LUT over d = qmax - q in [0,255], x = -d*ds ----
    float x = __fmul_rn(-(float)i, ds);
    // left constant: quant(exp(-40))
    float y = quant_i16(exp_f32(-40.0f), ESCALE);
    // region (-40,-20) line
    if (x >= -40.0f) {
        float y0 = exp_f32(-40.0f), y1 = exp_f32(-20.0f);
        float t = __fadd_rn(y0, __fmul_rn(__fadd_rn(x, 40.0f),
                                          __fdiv_rn(__fadd_rn(y1, -y0), 20.0f)));
        y = quant_i16(t, ESCALE);
    }
    // region (-20,-10) table
    if (x >= -20.0f) {
        float idxf = rintf(__fmul_rn(__fadd_rn(x, 20.0f), (float)(255.0 / 10.0)));
        idxf = fminf(fmaxf(idxf, 0.0f), 255.0f);
        float step = __fdiv_rn(10.0f, 255.0f);
        float xs = __fadd_rn(-20.0f, __fmul_rn(idxf, step));
        y = quant_i16(exp_f32(xs), ESCALE);
    }
    // region (-10,0) table
    if (x >= -10.0f) {
        float idxf = rintf(__fmul_rn(__fadd_rn(x, 10.0f), (float)(255.0 / 10.0)));
        idxf = fminf(fmaxf(idxf, 0.0f), 255.0f);
        float step = __fdiv_rn(10.0f, 255.0f);
        float xs = __fadd_rn(-10.0f, __fmul_rn(idxf, step));
        y = quant_i16(exp_f32(xs), ESCALE);
    }
    // region (0,1) line  (only d=0 reaches x==0)
    if (x >= 0.0f) {
        float y0 = exp_f32(0.0f), y1 = exp_f32(1.0f);
        float t = __fadd_rn(y0, __fmul_rn(x, __fdiv_rn(__fadd_rn(y1, -y0), 1.0f)));
        y = quant_i16(t, ESCALE);
    }
    if (x > 1.0f) y = quant_i16(exp_f32(1.0f), ESCALE);
    g_exp_lut[i] = y;

    // ---- recip tables (independent of ds) ----
    {
        float step1 = __fdiv_rn((float)(250.0 - 0.1), 255.0f);
        float xs1 = __fadd_rn(0.1f, __fmul_rn((float)i, step1));
        g_rtab1[i] = quant_i16(__fdiv_rn(1.0f, xs1), RSCALE);
        float step2 = __fdiv_rn(250.0f, 255.0f);
        float xs2 = __fadd_rn(250.0f, __fmul_rn((float)i, step2));
        g_rtab2[i] = quant_i16(__fdiv_rn(1.0f, xs2), RSCALE);
    }
}

__global__ __launch_bounds__(NTHREADS)
void quant_softmax_kernel(const int* __restrict__ in, float* __restrict__ out) {
    // 128 channels * 128 pixels * 2B = 32 KB (q pass, then overwritten by exp_q)
    __shared__ uint32_t sh[KROWS * NTHREADS];
    __shared__ float slut[256];

    int tid = threadIdx.x;
    slut[tid] = g_exp_lut[tid];
    slut[tid + 128] = g_exp_lut[tid + 128];
    __syncthreads();

    int tile = blockIdx.x;                 // b * 50 + tile_in_batch
    int b = tile / (HW_DIM / NTHREADS);
    int hw = (tile % (HW_DIM / NTHREADS)) * NTHREADS + tid;

    const int* p = in + (size_t)b * C_DIM * HW_DIM + hw;

    // ---- pass 1: channel max, stash q (int16x2 packed) in smem ----
    int m = -2147483647;
#pragma unroll 8
    for (int k = 0; k < KROWS; k++) {
        int q0 = p[(2 * k) * HW_DIM];
        int q1 = p[(2 * k + 1) * HW_DIM];
        m = max(m, max(q0, q1));
        sh[k * NTHREADS + tid] = (uint32_t)(q0 & 0xFFFF) | ((uint32_t)q1 << 16);
    }

    // ---- pass 2: exp LUT, sum; overwrite smem with exp_q (u16x2) ----
    float sum = 0.0f;
#pragma unroll 8
    for (int k = 0; k < KROWS; k++) {
        uint32_t w = sh[k * NTHREADS + tid];
        int d0 = m - (int)(short)(w & 0xFFFF);
        int d1 = m - (int)(short)(w >> 16);
        float e0 = slut[d0];
        float e1 = slut[d1];
        sum += e0 + e1;                    // all integers < 2^24: exact
        sh[k * NTHREADS + tid] = (uint32_t)(int)e0 | (((uint32_t)(int)e1) << 16);
    }

    // ---- reciprocal (per pixel) ----
    // shift = ceil(log2(128)) = 7
    float sum_sh = rintf(sum * 0.0078125f);                 // exact /128
    sum_sh = fminf(fmaxf(sum_sh, -32768.0f), 32767.0f);
    const float DIVSC = (float)(2.0 / 65535.0 * 128.0);
    float v = __fmul_rn(sum_sh, DIVSC);
    const float RSCALE = (float)((1.0 / 0.1) * 2.0 / 65535.0);

    float r = quant_i16(__fdiv_rn(1.0f, 0.001f), RSCALE);   // left const
    if (v >= 0.001f) {                                      // line (0.001,0.1)
        float y0 = __fdiv_rn(1.0f, 0.001f), y1 = __fdiv_rn(1.0f, 0.1f);
        float t = __fadd_rn(y0, __fmul_rn(__fadd_rn(v, -0.001f),
                                          __fdiv_rn(__fadd_rn(y1, -y0), (float)(0.1 - 0.001))));
        r = quant_i16(t, RSCALE);
    }
    if (v >= 0.1f) {                                        // table (0.1,250)
        float idxf = rintf(__fmul_rn(__fadd_rn(v, -0.1f), (float)(255.0 / 249.9)));
        idxf = fminf(fmaxf(idxf, 0.0f), 255.0f);
        r = g_rtab1[(int)idxf];
    }
    if (v >= 250.0f) {                                      // table (250,500)
        float idxf = rintf(__fmul_rn(__fadd_rn(v, -250.0f), (float)(255.0 / 250.0)));
        idxf = fminf(fmaxf(idxf, 0.0f), 255.0f);
        r = g_rtab2[(int)idxf];
    }
    if (v >= 500.0f) {                                      // line (500,700)
        float y0 = __fdiv_rn(1.0f, 500.0f), y1 = __fdiv_rn(1.0f, 700.0f);
        float t = __fadd_rn(y0, __fmul_rn(__fadd_rn(v, -500.0f),
                                          __fdiv_rn(__fadd_rn(y1, -y0), 200.0f)));
        r = quant_i16(t, RSCALE);
    }
    if (v > 700.0f) r = quant_i16(__fdiv_rn(1.0f, 700.0f), RSCALE);

    // ---- pass 3: out = clip(round((exp_q*recip_q)*K), i8) * OUT_SCALE ----
    const float KF = (float)((2.0 / 65535.0) * ((1.0 / 0.1) * 2.0 / 65535.0) / (2.0 / 255.0));
    const float OUTSC = (float)(2.0 / 255.0);
    float* po = out + (size_t)b * C_DIM * HW_DIM + hw;
#pragma unroll 8
    for (int k = 0; k < KROWS; k++) {
        uint32_t w = sh[k * NTHREADS + tid];
        float e0 = (float)(w & 0xFFFF);
        float e1 = (float)(w >> 16);
        float p0 = rintf(__fmul_rn(__fmul_rn(e0, r), KF));
        float p1 = rintf(__fmul_rn(__fmul_rn(e1, r), KF));
        p0 = fminf(fmaxf(p0, -128.0f), 127.0f);
        p1 = fminf(fmaxf(p1, -128.0f), 127.0f);
        po[(2 * k) * HW_DIM] = p0 * OUTSC;
        po[(2 * k + 1) * HW_DIM] = p1 * OUTSC;
    }
}

extern "C" void kernel_launch(void* const* d_in, const int* in_sizes, int n_in,
                              void* d_out, int out_size) {
    const int* data = (const int*)d_in[0];
    const float* data_scale = (const float*)d_in[1];
    float* out = (float*)d_out;

    build_luts_kernel<<<1, 256>>>(data_scale);

    int total = in_sizes[0];
    int B = total / (C_DIM * HW_DIM);
    int blocks = B * (HW_DIM / NTHREADS);
    quant_softmax_kernel<<<blocks, NTHREADS>>>(data, out);
}